// round 7
// baseline (speedup 1.0000x reference)
#include <cuda_runtime.h>
#include <cuda_bf16.h>

// MultiBoxLoss (SSD). 2-kernel pipeline:
//  A) stream: per-anchor CE -> g_ce scratch; per-chunk (32 anchors) positive
//     count + (posCE + smoothL1) partials. Coalesced float4 smem staging with
//     front-batched __ldcs LDGs. Block 0 zeroes the global accumulators.
//  B) per-row: reduce chunk partials -> k = min(3*npos, nneg); exact k-th
//     largest CE via 3-level radix histogram on float bit patterns with
//     warp-aggregated (__match_any_sync) smem atomics; sum top-k; last block
//     finalizes the output.

#define ROWS 128
#define AA   8732
#define CC   21
#define CPR  273            // chunks per row: 272 full (32) + 1 partial (28)
#define TOTCH (ROWS * CPR)  // 34944
#define WPB  8              // warps per block in phase A
#define BLKA (TOTCH / WPB)  // 4368
#define NTB  1024
#define PER  9              // ceil(8732/1024)

__device__ float  g_ce[ROWS * AA];      // ce_neg (0 for positives)
__device__ int    g_chunk_pos[TOTCH];
__device__ float  g_chunk_sum[TOTCH];   // posCE + smoothL1 partial per chunk
__device__ double g_sum;
__device__ unsigned long long g_npos;
__device__ unsigned g_done;

// ---------------------------------------------------------------- Phase A
__global__ __launch_bounds__(256) void mbl_phaseA(
    const float* __restrict__ conf,
    const float* __restrict__ loc,
    const int*   __restrict__ lab,
    const float* __restrict__ gloc)
{
    __shared__ float sbuf[WPB * 672];   // 21504 B

    if (blockIdx.x == 0 && threadIdx.x == 0) {
        g_sum = 0.0; g_npos = 0ull; g_done = 0u;
    }

    const int wid  = threadIdx.x >> 5;
    const int lane = threadIdx.x & 31;
    const int chunk = blockIdx.x * WPB + wid;
    const int row = chunk / CPR;
    const int j   = chunk - row * CPR;
    const int na  = (j == CPR - 1) ? (AA - (CPR - 1) * 32) : 32;  // 28 or 32
    const size_t abase = (size_t)row * AA + (size_t)j * 32;
    const size_t idx = abase + (size_t)lane;

    // Issue label load early so it overlaps staging.
    const int lb = (lane < na) ? __ldg(lab + idx) : 0;

    // Stage this chunk's logits: na*21 floats, contiguous & 16B-aligned.
    // Front-batch all LDGs into registers, then store to smem.
    float* sw = sbuf + wid * 672;
    const float4* src = (const float4*)(conf + abase * CC);
    const int n4 = (na * CC) >> 2;  // 168 or 147
    float4 q[6];
    #pragma unroll
    for (int i = 0; i < 6; i++) {
        const int t = lane + 32 * i;
        if (t < n4) q[i] = __ldcs(src + t);
    }
    #pragma unroll
    for (int i = 0; i < 6; i++) {
        const int t = lane + 32 * i;
        if (t < n4) ((float4*)sw)[t] = q[i];
    }
    __syncwarp();

    float cev = 0.f;    // ce_neg
    int   isp = 0;
    float psum = 0.f;   // posCE + smoothL1 contribution
    if (lane < na) {
        float v[CC];
        #pragma unroll
        for (int c = 0; c < CC; c++) v[c] = sw[lane * CC + c];

        float m = v[0];
        #pragma unroll
        for (int c = 1; c < CC; c++) m = fmaxf(m, v[c]);
        float s = 0.f;
        #pragma unroll
        for (int c = 0; c < CC; c++) s += __expf(v[c] - m);

        const float ce = m + __logf(s) - v[lb];

        if (lb > 0) {
            isp = 1;
            psum = ce;
            #pragma unroll
            for (int qd = 0; qd < 4; qd++) {
                const float d  = loc[idx * 4 + qd] - gloc[idx * 4 + qd];
                const float ad = fabsf(d);
                psum += (ad < 1.f) ? 0.5f * d * d : ad - 0.5f;
            }
        } else {
            cev = ce;   // strictly > 0 for finite logits
        }
        g_ce[idx] = cev;
    }

    // Warp-level chunk partials
    int pc = (int)__reduce_add_sync(0xFFFFFFFFu, (unsigned)isp);
    #pragma unroll
    for (int off = 16; off; off >>= 1)
        psum += __shfl_xor_sync(0xFFFFFFFFu, psum, off);
    if (lane == 0) {
        g_chunk_pos[chunk] = pc;
        g_chunk_sum[chunk] = psum;
    }
}

// ---------------------------------------------------------------- Phase B
// Warp-aggregated smem histogram add: lanes in 'mask' with equal 'bin' elect a
// leader that adds popc once.
__device__ __forceinline__ void hist_add(unsigned* h, unsigned bin, unsigned mask)
{
    const unsigned peers  = __match_any_sync(mask, bin);
    const unsigned leader = __ffs(peers) - 1u;
    if ((threadIdx.x & 31u) == leader)
        atomicAdd(&h[bin], __popc(peers));
}

// warp-0 helper: scan bins descending from startbin, find the bin where the
// cumulative count reaches rank r; write bin index + rank-within-bin to smem.
__device__ __forceinline__ void find_bin_w0(
    const unsigned* __restrict__ h, int startbin, unsigned r,
    int* selbin, unsigned* selrank, unsigned lane)
{
    unsigned run = 0;
    for (int base = startbin; base >= 0; base -= 32) {
        const int bin = base - (int)lane;     // lane0 = highest
        unsigned c = (bin >= 0) ? h[bin] : 0u;
        unsigned pre = c;
        #pragma unroll
        for (int off = 1; off < 32; off <<= 1) {
            const unsigned x = __shfl_up_sync(0xFFFFFFFFu, pre, off);
            if (lane >= off) pre += x;
        }
        const unsigned cum = run + pre;
        const unsigned ball = __ballot_sync(0xFFFFFFFFu, cum >= r);
        if (ball) {
            const int l = __ffs((int)ball) - 1;     // first (highest) bin
            const unsigned cum_l = __shfl_sync(0xFFFFFFFFu, cum, l);
            const unsigned c_l   = __shfl_sync(0xFFFFFFFFu, c,   l);
            if (lane == 0) {
                *selbin  = base - l;
                *selrank = r - (cum_l - c_l);
            }
            return;
        }
        run = __shfl_sync(0xFFFFFFFFu, cum, 31);
    }
    if (lane == 0) { *selbin = 0; *selrank = 1u; }  // unreachable
}

__global__ __launch_bounds__(NTB) void mbl_phaseB(float* __restrict__ out)
{
    const int b    = blockIdx.x;
    const int tid  = threadIdx.x;
    const unsigned lane = tid & 31u;

    __shared__ unsigned s_hist[2048];
    __shared__ int      s_selbin;
    __shared__ unsigned s_selrank;
    __shared__ int      s_pos;
    __shared__ double   s_psum;
    __shared__ float    s_fsum;
    __shared__ unsigned s_cgt;
    __shared__ unsigned s_maxb;

    if (tid == 0) { s_pos = 0; s_psum = 0.0; s_fsum = 0.f; s_cgt = 0u; s_maxb = 0u; }

    // Front-issue this row's ce_neg loads (L2-resident) to overlap the
    // partials reduction below.
    float ce[PER];
    #pragma unroll
    for (int i = 0; i < PER; i++) {
        const int a = tid + i * NTB;
        ce[i] = (a < AA) ? g_ce[(size_t)b * AA + a] : 0.f;
    }

    // Reduce this row's chunk partials (273 of them).
    {
        int   pc = 0;
        float ps = 0.f;
        if (tid < CPR) {
            pc = g_chunk_pos[b * CPR + tid];
            ps = g_chunk_sum[b * CPR + tid];
        }
        pc = (int)__reduce_add_sync(0xFFFFFFFFu, (unsigned)pc);
        #pragma unroll
        for (int off = 16; off; off >>= 1)
            ps += __shfl_down_sync(0xFFFFFFFFu, ps, off);
        if (lane == 0) {
            atomicAdd(&s_pos, pc);
            atomicAdd(&s_psum, (double)ps);
        }
    }

    unsigned bits[PER];
    unsigned mb = 0u;
    #pragma unroll
    for (int i = 0; i < PER; i++) {
        bits[i] = __float_as_uint(ce[i]);
        mb = max(mb, bits[i]);
    }
    mb = __reduce_max_sync(0xFFFFFFFFu, mb);
    if (lane == 0) atomicMax(&s_maxb, mb);
    __syncthreads();

    const int npos = s_pos;
    const int k = min(3 * npos, AA - npos);
    const unsigned maxbits = s_maxb;

    double negsum = 0.0;
    if (k > 0) {
        unsigned r = (unsigned)k;

        // ---- Level 1: bits[30:21] ----
        s_hist[tid] = 0u;
        __syncthreads();
        #pragma unroll
        for (int i = 0; i < PER; i++)
            hist_add(s_hist, bits[i] >> 21, 0xFFFFFFFFu);
        __syncthreads();
        if (tid < 32)
            find_bin_w0(s_hist, (int)(maxbits >> 21), r, &s_selbin, &s_selrank, lane);
        __syncthreads();
        const unsigned B1 = (unsigned)s_selbin;
        r = s_selrank;
        __syncthreads();

        // ---- Level 2: bits[20:11] among bin1 == B1 ----
        s_hist[tid] = 0u;
        __syncthreads();
        #pragma unroll
        for (int i = 0; i < PER; i++) {
            const bool act = ((bits[i] >> 21) == B1);
            const unsigned mask = __ballot_sync(0xFFFFFFFFu, act);
            if (act) hist_add(s_hist, (bits[i] >> 11) & 1023u, mask);
        }
        __syncthreads();
        if (tid < 32) find_bin_w0(s_hist, 1023, r, &s_selbin, &s_selrank, lane);
        __syncthreads();
        const unsigned top21 = (B1 << 10) | (unsigned)s_selbin;
        r = s_selrank;
        __syncthreads();

        // ---- Level 3: bits[10:0] among top21 match ----
        s_hist[tid] = 0u;
        s_hist[tid + 1024] = 0u;
        __syncthreads();
        #pragma unroll
        for (int i = 0; i < PER; i++) {
            const bool act = ((bits[i] >> 11) == top21);
            const unsigned mask = __ballot_sync(0xFFFFFFFFu, act);
            if (act) hist_add(s_hist, bits[i] & 2047u, mask);
        }
        __syncthreads();
        if (tid < 32) find_bin_w0(s_hist, 2047, r, &s_selbin, &s_selrank, lane);
        __syncthreads();

        const unsigned vbits = (top21 << 11) | (unsigned)s_selbin;
        const float    vth   = __uint_as_float(vbits);

        // sum of values strictly greater + tie fill at threshold
        float    fs  = 0.f;
        unsigned cgt = 0u;
        #pragma unroll
        for (int i = 0; i < PER; i++)
            if (bits[i] > vbits) { fs += ce[i]; cgt++; }
        cgt = __reduce_add_sync(0xFFFFFFFFu, cgt);
        #pragma unroll
        for (int off = 16; off; off >>= 1)
            fs += __shfl_down_sync(0xFFFFFFFFu, fs, off);
        if (lane == 0) {
            atomicAdd(&s_fsum, fs);
            atomicAdd(&s_cgt, cgt);
        }
        __syncthreads();
        negsum = (double)s_fsum + (double)(k - (int)s_cgt) * (double)vth;
    }

    if (tid == 0) {
        atomicAdd(&g_sum, s_psum + negsum);
        atomicAdd(&g_npos, (unsigned long long)npos);
        __threadfence();
        const unsigned done = atomicAdd(&g_done, 1u);
        if (done == ROWS - 1) {
            __threadfence();
            const double ts = atomicAdd(&g_sum, 0.0);
            const unsigned long long tp = atomicAdd(&g_npos, 0ull);
            out[0] = (float)(ts / (double)tp);
        }
    }
}

extern "C" void kernel_launch(void* const* d_in, const int* in_sizes, int n_in,
                              void* d_out, int out_size)
{
    const float* conf = (const float*)d_in[0];
    const float* loc  = (const float*)d_in[1];
    const int*   lab  = (const int*)  d_in[2];
    const float* gloc = (const float*)d_in[3];
    float* out = (float*)d_out;

    mbl_phaseA<<<BLKA, 256>>>(conf, loc, lab, gloc);
    mbl_phaseB<<<ROWS, NTB>>>(out);
}

// round 10
// speedup vs baseline: 1.2221x; 1.2221x over previous
#include <cuda_runtime.h>
#include <cuda_bf16.h>

// MultiBoxLoss (SSD). 2-kernel pipeline:
//  A) stream: per-anchor CE -> g_ce scratch; per-chunk (32 anchors) positive
//     count + (posCE + smoothL1) partials. Coalesced float4 smem staging with
//     front-batched __ldcs LDGs. Block 0 zeroes the global accumulators.
//  B) per-row: reduce chunk partials -> k = min(3*npos, nneg); k-th largest
//     CE via block-parallel 3-level radix histogram (11/10/10 bits), EXACTLY
//     validated (count(>v) < k <= count(>=v)); bisection fallback if the
//     validation fails. Sum top-k; last block finalizes the output.

#define ROWS 128
#define AA   8732
#define CC   21
#define CPR  273            // chunks per row: 272 full (32) + 1 partial (28)
#define TOTCH (ROWS * CPR)  // 34944
#define WPB  8              // warps per block in phase A
#define BLKA (TOTCH / WPB)  // 4368
#define NTB  1024
#define PER  9              // ceil(8732/1024)

__device__ float  g_ce[ROWS * AA];      // ce_neg (0 for positives)
__device__ int    g_chunk_pos[TOTCH];
__device__ float  g_chunk_sum[TOTCH];   // posCE + smoothL1 partial per chunk
__device__ double g_sum;
__device__ unsigned long long g_npos;
__device__ unsigned g_done;

// ---------------------------------------------------------------- Phase A
__global__ __launch_bounds__(256) void mbl_phaseA(
    const float* __restrict__ conf,
    const float* __restrict__ loc,
    const int*   __restrict__ lab,
    const float* __restrict__ gloc)
{
    __shared__ float sbuf[WPB * 672];   // 21504 B

    if (blockIdx.x == 0 && threadIdx.x == 0) {
        g_sum = 0.0; g_npos = 0ull; g_done = 0u;
    }

    const int wid  = threadIdx.x >> 5;
    const int lane = threadIdx.x & 31;
    const int chunk = blockIdx.x * WPB + wid;
    const int row = chunk / CPR;
    const int j   = chunk - row * CPR;
    const int na  = (j == CPR - 1) ? (AA - (CPR - 1) * 32) : 32;  // 28 or 32
    const size_t abase = (size_t)row * AA + (size_t)j * 32;
    const size_t idx = abase + (size_t)lane;

    // Issue label load early so it overlaps staging.
    const int lb = (lane < na) ? __ldg(lab + idx) : 0;

    // Stage this chunk's logits: na*21 floats, contiguous & 16B-aligned.
    // Front-batch all LDGs into registers, then store to smem.
    float* sw = sbuf + wid * 672;
    const float4* src = (const float4*)(conf + abase * CC);
    const int n4 = (na * CC) >> 2;  // 168 or 147
    float4 q[6];
    #pragma unroll
    for (int i = 0; i < 6; i++) {
        const int t = lane + 32 * i;
        if (t < n4) q[i] = __ldcs(src + t);
    }
    #pragma unroll
    for (int i = 0; i < 6; i++) {
        const int t = lane + 32 * i;
        if (t < n4) ((float4*)sw)[t] = q[i];
    }
    __syncwarp();

    float cev = 0.f;    // ce_neg
    int   isp = 0;
    float psum = 0.f;   // posCE + smoothL1 contribution
    if (lane < na) {
        float v[CC];
        #pragma unroll
        for (int c = 0; c < CC; c++) v[c] = sw[lane * CC + c];

        float m = v[0];
        #pragma unroll
        for (int c = 1; c < CC; c++) m = fmaxf(m, v[c]);
        float s = 0.f;
        #pragma unroll
        for (int c = 0; c < CC; c++) s += __expf(v[c] - m);

        const float ce = m + __logf(s) - v[lb];

        if (lb > 0) {
            isp = 1;
            psum = ce;
            #pragma unroll
            for (int qd = 0; qd < 4; qd++) {
                const float d  = loc[idx * 4 + qd] - gloc[idx * 4 + qd];
                const float ad = fabsf(d);
                psum += (ad < 1.f) ? 0.5f * d * d : ad - 0.5f;
            }
        } else {
            cev = ce;   // strictly > 0 for finite logits
        }
        g_ce[idx] = cev;
    }

    // Warp-level chunk partials
    int pc = (int)__reduce_add_sync(0xFFFFFFFFu, (unsigned)isp);
    #pragma unroll
    for (int off = 16; off; off >>= 1)
        psum += __shfl_xor_sync(0xFFFFFFFFu, psum, off);
    if (lane == 0) {
        g_chunk_pos[chunk] = pc;
        g_chunk_sum[chunk] = psum;
    }
}

// ---------------------------------------------------------------- Phase B
// Warp-aggregated smem histogram add.
__device__ __forceinline__ void hist_add(unsigned* h, unsigned bin, unsigned mask)
{
    const unsigned peers  = __match_any_sync(mask, bin);
    const unsigned leader = __ffs(peers) - 1u;
    if ((threadIdx.x & 31u) == leader)
        atomicAdd(&h[bin], __popc(peers));
}

// Block-wide inclusive prefix sum over 1024 values (one per thread).
// Contains 2 __syncthreads. s_w must hold 32 unsigneds.
__device__ __forceinline__ unsigned block_scan_incl(
    unsigned v, unsigned* s_w, int wid, unsigned lane)
{
    #pragma unroll
    for (int off = 1; off < 32; off <<= 1) {
        const unsigned x = __shfl_up_sync(0xFFFFFFFFu, v, off);
        if (lane >= off) v += x;
    }
    if (lane == 31) s_w[wid] = v;
    __syncthreads();
    if (wid == 0) {
        unsigned t = s_w[lane];
        #pragma unroll
        for (int off = 1; off < 32; off <<= 1) {
            const unsigned x = __shfl_up_sync(0xFFFFFFFFu, t, off);
            if (lane >= off) t += x;
        }
        s_w[lane] = t;  // inclusive warp totals
    }
    __syncthreads();
    if (wid > 0) v += s_w[wid - 1];
    return v;
}

__global__ __launch_bounds__(NTB) void mbl_phaseB(float* __restrict__ out)
{
    const int b    = blockIdx.x;
    const int tid  = threadIdx.x;
    const int wid  = tid >> 5;
    const unsigned lane = tid & 31u;

    __shared__ unsigned s_hist[2048];
    __shared__ unsigned s_w[32];
    __shared__ int      s_selbin;
    __shared__ unsigned s_selrank;
    __shared__ int      s_pos;
    __shared__ double   s_psum;
    __shared__ float    s_fsum;
    __shared__ unsigned s_cgt;
    __shared__ unsigned s_vgt, s_vge;   // validation counters

    if (tid == 0) {
        s_pos = 0; s_psum = 0.0; s_fsum = 0.f; s_cgt = 0u;
        s_vgt = 0u; s_vge = 0u;
    }
    __syncthreads();   // init visible before any smem atomics below

    // Front-issue this row's ce_neg loads to overlap the partials reduction.
    float ce[PER];
    #pragma unroll
    for (int i = 0; i < PER; i++) {
        const int a = tid + i * NTB;
        ce[i] = (a < AA) ? g_ce[(size_t)b * AA + a] : 0.f;
    }

    // Reduce this row's chunk partials (273 of them).
    {
        int   pc = 0;
        float ps = 0.f;
        if (tid < CPR) {
            pc = g_chunk_pos[b * CPR + tid];
            ps = g_chunk_sum[b * CPR + tid];
        }
        pc = (int)__reduce_add_sync(0xFFFFFFFFu, (unsigned)pc);
        #pragma unroll
        for (int off = 16; off; off >>= 1)
            ps += __shfl_down_sync(0xFFFFFFFFu, ps, off);
        if (lane == 0) {
            atomicAdd(&s_pos, pc);
            atomicAdd(&s_psum, (double)ps);
        }
    }

    unsigned bits[PER];
    #pragma unroll
    for (int i = 0; i < PER; i++) bits[i] = __float_as_uint(ce[i]);

    // Zero level-1 histogram (2048 bins) while waiting.
    s_hist[tid] = 0u;
    s_hist[tid + 1024] = 0u;
    __syncthreads();

    const int npos = s_pos;
    const int k = min(3 * npos, AA - npos);   // uniform across block

    double negsum = 0.0;
    if (k > 0) {
        unsigned r = (unsigned)k;

        // ---- Level 1: bits[30:20], 2048 bins (2 per thread, pair scan) ----
        #pragma unroll
        for (int i = 0; i < PER; i++)
            hist_add(s_hist, bits[i] >> 20, 0xFFFFFFFFu);
        __syncthreads();
        {
            const int p = 1023 - tid;               // pair index, tid0 = topmost
            const unsigned h_hi = s_hist[2 * p + 1];
            const unsigned h_lo = s_hist[2 * p];
            const unsigned P = h_hi + h_lo;
            const unsigned cum = block_scan_incl(P, s_w, wid, lane);
            const unsigned above = cum - P;         // count strictly above pair
            if (cum >= r && above < r) {
                if (above + h_hi >= r) { s_selbin = 2 * p + 1; s_selrank = r - above; }
                else                   { s_selbin = 2 * p;     s_selrank = r - above - h_hi; }
            }
        }
        __syncthreads();
        const unsigned B1 = (unsigned)s_selbin;
        r = s_selrank;
        __syncthreads();

        // ---- Level 2: bits[19:10] among level-1 bin == B1 ----
        s_hist[tid] = 0u;
        __syncthreads();
        #pragma unroll
        for (int i = 0; i < PER; i++) {
            const bool act = ((bits[i] >> 20) == B1);
            const unsigned mask = __ballot_sync(0xFFFFFFFFu, act);
            if (act) hist_add(s_hist, (bits[i] >> 10) & 1023u, mask);
        }
        __syncthreads();
        {
            const int bin = 1023 - tid;
            const unsigned h = s_hist[bin];
            const unsigned cum = block_scan_incl(h, s_w, wid, lane);
            if (cum >= r && cum - h < r) { s_selbin = bin; s_selrank = r - (cum - h); }
        }
        __syncthreads();
        const unsigned top21 = (B1 << 10) | (unsigned)s_selbin;
        r = s_selrank;
        __syncthreads();

        // ---- Level 3: bits[9:0] among top-21-bit match ----
        s_hist[tid] = 0u;
        __syncthreads();
        #pragma unroll
        for (int i = 0; i < PER; i++) {
            const bool act = ((bits[i] >> 10) == top21);
            const unsigned mask = __ballot_sync(0xFFFFFFFFu, act);
            if (act) hist_add(s_hist, bits[i] & 1023u, mask);
        }
        __syncthreads();
        {
            const int bin = 1023 - tid;
            const unsigned h = s_hist[bin];
            const unsigned cum = block_scan_incl(h, s_w, wid, lane);
            if (cum >= r && cum - h < r) { s_selbin = bin; s_selrank = r - (cum - h); }
        }
        // Zero the first 64 hist slots for a possible bisection fallback.
        if (tid < 64) s_hist[tid + 1024] = 0u;   // use upper region, untouched below
        __syncthreads();

        unsigned vbits = (top21 << 10) | (unsigned)s_selbin;

        // ---- Exact validation: count(>v) < k <= count(>=v) ----
        {
            unsigned cgt = 0u, cge = 0u;
            #pragma unroll
            for (int i = 0; i < PER; i++) {
                cgt += (bits[i] >  vbits) ? 1u : 0u;
                cge += (bits[i] >= vbits) ? 1u : 0u;
            }
            cgt = __reduce_add_sync(0xFFFFFFFFu, cgt);
            cge = __reduce_add_sync(0xFFFFFFFFu, cge);
            if (lane == 0) {
                atomicAdd(&s_vgt, cgt);
                atomicAdd(&s_vge, cge);
            }
        }
        __syncthreads();
        const bool valid = (s_vgt < (unsigned)k) && (s_vge >= (unsigned)k);

        if (!valid) {
            // ---- Fallback: bisection on float bits (known-correct) ----
            unsigned lo = 0u, hi = 0x7F800000u;
            int iter = 0;
            while (lo < hi) {
                const unsigned mid = (lo + hi) >> 1;
                unsigned c = 0;
                #pragma unroll
                for (int i = 0; i < PER; i++) c += (bits[i] > mid) ? 1u : 0u;
                c = __reduce_add_sync(0xFFFFFFFFu, c);
                if (lane == 0) atomicAdd(&s_hist[1024 + iter], c);
                __syncthreads();
                const unsigned tot = s_hist[1024 + iter];
                if (tot < (unsigned)k) hi = mid; else lo = mid + 1u;
                iter++;
            }
            vbits = lo;
        }

        const float vth = __uint_as_float(vbits);

        // sum of values strictly greater + tie fill at threshold
        float    fs  = 0.f;
        unsigned cgt = 0u;
        #pragma unroll
        for (int i = 0; i < PER; i++)
            if (bits[i] > vbits) { fs += ce[i]; cgt++; }
        cgt = __reduce_add_sync(0xFFFFFFFFu, cgt);
        #pragma unroll
        for (int off = 16; off; off >>= 1)
            fs += __shfl_down_sync(0xFFFFFFFFu, fs, off);
        if (lane == 0) {
            atomicAdd(&s_fsum, fs);
            atomicAdd(&s_cgt, cgt);
        }
        __syncthreads();
        negsum = (double)s_fsum + (double)(k - (int)s_cgt) * (double)vth;
    }

    if (tid == 0) {
        atomicAdd(&g_sum, s_psum + negsum);
        atomicAdd(&g_npos, (unsigned long long)npos);
        __threadfence();
        const unsigned done = atomicAdd(&g_done, 1u);
        if (done == ROWS - 1) {
            __threadfence();
            const double ts = atomicAdd(&g_sum, 0.0);
            const unsigned long long tp = atomicAdd(&g_npos, 0ull);
            out[0] = (float)(ts / (double)tp);
        }
    }
}

extern "C" void kernel_launch(void* const* d_in, const int* in_sizes, int n_in,
                              void* d_out, int out_size)
{
    const float* conf = (const float*)d_in[0];
    const float* loc  = (const float*)d_in[1];
    const int*   lab  = (const int*)  d_in[2];
    const float* gloc = (const float*)d_in[3];
    float* out = (float*)d_out;

    mbl_phaseA<<<BLKA, 256>>>(conf, loc, lab, gloc);
    mbl_phaseB<<<ROWS, NTB>>>(out);
}